// round 8
// baseline (speedup 1.0000x reference)
#include <cuda_runtime.h>
#include <cuda_fp16.h>
#include <cstdint>

#define N_GENES 16384
#define N_REG   8192
#define D_MODEL 256
#define OUT_DIM 128
#define ALPHA   0.2f

#define TI 64                  // regulon rows per CTA
#define TJ 32                  // j per tile (MMA K)
#define JSPLIT 2
#define NJ (N_GENES / JSPLIT)  // 8192 j per CTA
#define NT (NJ / TJ)           // 256 tiles
#define STAGES 4

// smem layout (per CTA 68 KB -> 3 CTAs/SM)
#define SM_P    0                      // 4 KB P (single buffer, 64x32 fp16, 64B rows SW64)
#define SM_ADJ  4096                   // 4 x 8 KB adj stages (64 rows x 128 B, swizzled)
#define SM_V    36864                  // 4 x 8 KB V stages (fp16, 2 atoms of 32x128B)
#define SMEM_BYTES 69632

// ---------------- device scratch ----------------
__device__ float  g_wh [N_GENES * OUT_DIM];
__device__ __align__(16) __half g_whh[N_GENES * OUT_DIM];   // w_h fp16, row-major
__device__ float  g_wh1[N_REG];
__device__ float  g_wh2[N_GENES];
__device__ __align__(16) float g_F12[2 * N_GENES];          // interleaved {F1[j], F2[j]}
__device__ float  g_G1 [N_REG];
__device__ float  g_G2 [N_REG];
__device__ unsigned g_w2max_bits;
__device__ float  g_Dp [JSPLIT][(size_t)N_REG * OUT_DIM];   // partial D
__device__ float  g_Sp [JSPLIT][N_REG];                     // partial S

// ---------------- helpers ----------------
static __device__ __forceinline__ uint32_t swz(uint32_t x)   { return x ^ ((x >> 3) & 0x70); }
static __device__ __forceinline__ uint32_t swz64(uint32_t x) { return x ^ ((x >> 3) & 0x30); }
static __device__ __forceinline__ uint32_t smem_u32(const void* p) {
    return (uint32_t)__cvta_generic_to_shared(p);
}
static __device__ __forceinline__ uint64_t pk2(float x, float y) {
    uint64_t r; asm("mov.b64 %0, {%1, %2};" : "=l"(r) : "f"(x), "f"(y)); return r;
}
static __device__ __forceinline__ void fma2(uint64_t& acc, uint64_t a, uint64_t b) {
    asm volatile("fma.rn.f32x2 %0, %1, %2, %0;" : "+l"(acc) : "l"(a), "l"(b));
}
static __device__ __forceinline__ unsigned fenc(float f) {
    unsigned u = __float_as_uint(f);
    return (u & 0x80000000u) ? ~u : (u | 0x80000000u);
}
static __device__ __forceinline__ float fdec(unsigned k) {
    unsigned u = (k & 0x80000000u) ? (k ^ 0x80000000u) : ~k;
    return __uint_as_float(u);
}

// ---------------- K1: w_h = input @ weights ----------------
__global__ void k_gemm1(const float* __restrict__ inp, const float* __restrict__ W) {
    __shared__ __align__(16) float s_t[D_MODEL][8];   // [k][r]
    const int c  = threadIdx.x;
    const int r0 = blockIdx.x * 8;
    if (blockIdx.x == 0 && c == 0) g_w2max_bits = 0u;
    #pragma unroll
    for (int u = 0; u < 16; u++) {
        const int idx = c + u * 128;
        const int r = idx >> 8, k = idx & 255;
        s_t[k][r] = inp[(size_t)(r0 + r) * D_MODEL + k];
    }
    __syncthreads();

    uint64_t a01 = 0, a23 = 0, a45 = 0, a67 = 0;
    #pragma unroll 4
    for (int k = 0; k < D_MODEL; k++) {
        const float w = __ldg(&W[k * OUT_DIM + c]);
        const uint64_t ww = pk2(w, w);
        ulonglong2 lo = *(const ulonglong2*)&s_t[k][0];
        ulonglong2 hi = *(const ulonglong2*)&s_t[k][4];
        fma2(a01, lo.x, ww);
        fma2(a23, lo.y, ww);
        fma2(a45, hi.x, ww);
        fma2(a67, hi.y, ww);
    }
    float v[8];
    v[0] = __uint_as_float((uint32_t)a01); v[1] = __uint_as_float((uint32_t)(a01 >> 32));
    v[2] = __uint_as_float((uint32_t)a23); v[3] = __uint_as_float((uint32_t)(a23 >> 32));
    v[4] = __uint_as_float((uint32_t)a45); v[5] = __uint_as_float((uint32_t)(a45 >> 32));
    v[6] = __uint_as_float((uint32_t)a67); v[7] = __uint_as_float((uint32_t)(a67 >> 32));
    #pragma unroll
    for (int r = 0; r < 8; r++) {
        g_wh [(size_t)(r0 + r) * OUT_DIM + c] = v[r];
        g_whh[(size_t)(r0 + r) * OUT_DIM + c] = __float2half(v[r]);
    }
}

// ---------------- K2: wh1, wh2 + global max(wh2) ----------------
__global__ void k_wh12(const float* __restrict__ a) {
    __shared__ float sred[8];
    const int warp = threadIdx.x >> 5;
    const int row  = blockIdx.x * 8 + warp;
    const int lane = threadIdx.x & 31;
    const float* r = g_wh + (size_t)row * OUT_DIM;
    float s1 = 0.f, s2 = 0.f;
    #pragma unroll
    for (int c = lane; c < OUT_DIM; c += 32) {
        float v = r[c];
        s1 = fmaf(v, a[c], s1);
        s2 = fmaf(v, a[OUT_DIM + c], s2);
    }
    #pragma unroll
    for (int o = 16; o; o >>= 1) {
        s1 += __shfl_xor_sync(0xffffffffu, s1, o);
        s2 += __shfl_xor_sync(0xffffffffu, s2, o);
    }
    if (lane == 0) {
        if (row < N_REG) g_wh1[row] = s1;
        g_wh2[row] = s2;
        sred[warp] = s2;
    }
    __syncthreads();
    if (threadIdx.x == 0) {
        float m = sred[0];
        #pragma unroll
        for (int w = 1; w < 8; w++) m = fmaxf(m, sred[w]);
        atomicMax(&g_w2max_bits, fenc(m));
    }
}

// ---------------- K3: exp factor tables ----------------
__global__ void k_factors() {
    const int j = blockIdx.x * 256 + threadIdx.x;
    const float w2m = fdec(g_w2max_bits);
    if (j < N_GENES) {
        float w2 = g_wh2[j];
        g_F12[2 * j]     = expf(w2);
        g_F12[2 * j + 1] = expf(ALPHA * w2);
    }
    if (j < N_REG) {
        float w1 = g_wh1[j];
        float x  = w1 + w2m;
        float B  = x > 0.f ? x : ALPHA * x;
        g_G1[j] = expf(w1 - B);
        g_G2[j] = expf(ALPHA * w1 - B);
    }
}

// ---------------- K4: fused masked-softmax attention ----------------
__global__ void __launch_bounds__(256, 3)
k_attn(const float* __restrict__ adj) {
    extern __shared__ char smem[];
    const uint32_t sb = smem_u32(smem);
    const uint32_t PB = sb + SM_P;

    const int t    = threadIdx.x;
    const int lane = t & 31, warp = t >> 5;   // 8 warps
    const int i0   = (blockIdx.x >> 1) * TI;
    const int jh   = blockIdx.x & 1;
    const int j0b  = jh * NJ;
    const int rh   = lane >> 4;               // row half within warp's 8 rows
    const int q    = lane & 15;               // col pair (2 cols of 32)

    const float* adjbase = adj + (size_t)i0 * N_GENES + j0b;

    // one stage = adj tile (64x32 f32, 8 KB) + V tile (32x128 f16, 8 KB); always commits
    auto load_stage = [&](int jt) {
        if (jt < NT) {
            const int st = jt & (STAGES - 1);
            const int jo = jt * TJ;
            const uint32_t AB = sb + SM_ADJ + st * 8192;
            const uint32_t VB = sb + SM_V   + st * 8192;
            #pragma unroll
            for (int u = 0; u < 2; u++) {
                const int idx = t + u * 256;
                {   // adj: row = idx>>3 (0..63), 16B chunk = idx&7
                    const int row = idx >> 3, ch = idx & 7;
                    const float* src = adjbase + (size_t)row * N_GENES + jo + ch * 4;
                    asm volatile("cp.async.cg.shared.global [%0], [%1], 16;"
                                 :: "r"(AB + swz(row * 128 + ch * 16)), "l"(src));
                }
                {   // V: row = idx>>4 (0..31), seg = idx&15; 2 atoms of 32x128B
                    const int row = idx >> 4, seg = idx & 15;
                    const __half* src = &g_whh[(size_t)(j0b + jo + row) * OUT_DIM + seg * 8];
                    const uint32_t dst = VB + (seg >> 3) * 4096 + swz(row * 128 + (seg & 7) * 16);
                    asm volatile("cp.async.cg.shared.global [%0], [%1], 16;" :: "r"(dst), "l"(src));
                }
            }
        }
        asm volatile("cp.async.commit_group;" ::: "memory");
    };

    // P-build row constants (rows warp*8 + rh*4 + r)
    float Tr[4], G1r[4], G2r[4], sacc[4];
    #pragma unroll
    for (int r = 0; r < 4; r++) {
        const int i = i0 + warp * 8 + rh * 4 + r;
        Tr[r]  = g_wh1[i];
        G1r[r] = g_G1[i];
        G2r[r] = g_G2[i];
        sacc[r] = 0.f;
    }

    // MMA tiling: warp -> rows wi*32 (2 m16 frags), cols wc*32
    const int wi = warp >> 2, wc = warp & 3;
    float d[2][4][4];
    #pragma unroll
    for (int ah = 0; ah < 2; ah++)
        #pragma unroll
        for (int n = 0; n < 4; n++)
            #pragma unroll
            for (int k = 0; k < 4; k++) d[ah][n][k] = 0.f;

    uint32_t dh[2][4][2];
    #pragma unroll
    for (int ah = 0; ah < 2; ah++)
        #pragma unroll
        for (int n = 0; n < 4; n++) { dh[ah][n][0] = 0u; dh[ah][n][1] = 0u; }

    // prologue: fill 3 stages
    load_stage(0);
    load_stage(1);
    load_stage(2);

    for (int jt = 0; jt < NT; jt++) {
        const int st = jt & (STAGES - 1);
        const uint32_t AB = sb + SM_ADJ + st * 8192;
        const uint32_t VB = sb + SM_V   + st * 8192;

        asm volatile("cp.async.wait_group 2;" ::: "memory");
        __syncthreads();   // stage jt visible; P free (last iter's MMA reads done)

        load_stage(jt + 3);   // slot (jt-1)&3, freed

        // ---- build P tile (4 rows x 2 cols per thread) from smem adj ----
        const int jo = jt * TJ;
        const float2 w2q = *(const float2*)&g_wh2[j0b + jo + q * 2];
        const float4 fq  = *(const float4*)&g_F12[2 * (j0b + jo + q * 2)];   // F1,F2 x 2 cols
        #pragma unroll
        for (int r = 0; r < 4; r++) {
            const int prow = warp * 8 + rh * 4 + r;
            float2 a2;
            asm volatile("ld.shared.v2.f32 {%0,%1}, [%2];"
                         : "=f"(a2.x), "=f"(a2.y) : "r"(AB + swz(prow * 128 + q * 8)));
            const float T = Tr[r], G1 = G1r[r], G2 = G2r[r];
            float x0 = T + w2q.x, x1 = T + w2q.y;
            float e0 = fmaxf(G1 * fq.x, G2 * fq.y);   // exp(lrelu(x)-B), monotone split
            float e1 = fmaxf(G1 * fq.z, G2 * fq.w);
            float p0 = (a2.x != 0.f && x0 != 0.f) ? e0 : 0.f;
            float p1 = (a2.y != 0.f && x1 != 0.f) ? e1 : 0.f;
            sacc[r] += p0 + p1;
            __half2 h = __floats2half2_rn(p0, p1);
            asm volatile("st.shared.b32 [%0], %1;"
                         :: "r"(PB + swz64(prow * 64 + q * 4)), "r"(*(uint32_t*)&h));
        }
        __syncthreads();   // P complete

        // ---- MMA: D(32x32 per warp) += P(32x32) @ V(32x32), fp16 accumulate ----
        #pragma unroll
        for (int ks = 0; ks < 2; ks++) {
            uint32_t afr[2][4];
            #pragma unroll
            for (int ah = 0; ah < 2; ah++) {
                const uint32_t aaddr = PB + swz64((wi * 32 + ah * 16 + (lane & 15)) * 64
                                                  + ks * 32 + (lane >> 4) * 16);
                asm volatile("ldmatrix.sync.aligned.m8n8.x4.shared.b16 {%0,%1,%2,%3},[%4];\n"
                             : "=r"(afr[ah][0]), "=r"(afr[ah][1]),
                               "=r"(afr[ah][2]), "=r"(afr[ah][3]) : "r"(aaddr));
            }
            uint32_t bfr[8];
            const int atom = wc >> 1;
            const int cin0 = (wc & 1) * 32 + (lane >> 4) * 8;
            const uint32_t brow = (ks * 16 + (lane & 15)) * 128;
            const uint32_t baddr0 = VB + atom * 4096 + swz(brow + cin0 * 2);
            asm volatile("ldmatrix.sync.aligned.m8n8.x4.trans.shared.b16 {%0,%1,%2,%3},[%4];\n"
                         : "=r"(bfr[0]), "=r"(bfr[1]), "=r"(bfr[2]), "=r"(bfr[3]) : "r"(baddr0));
            const uint32_t baddr1 = VB + atom * 4096 + swz(brow + (cin0 + 16) * 2);
            asm volatile("ldmatrix.sync.aligned.m8n8.x4.trans.shared.b16 {%0,%1,%2,%3},[%4];\n"
                         : "=r"(bfr[4]), "=r"(bfr[5]), "=r"(bfr[6]), "=r"(bfr[7]) : "r"(baddr1));
            #pragma unroll
            for (int ah = 0; ah < 2; ah++)
                #pragma unroll
                for (int n = 0; n < 4; n++) {
                    asm volatile(
                        "mma.sync.aligned.m16n8k16.row.col.f16.f16.f16.f16 "
                        "{%0,%1},{%2,%3,%4,%5},{%6,%7},{%0,%1};\n"
                        : "+r"(dh[ah][n][0]), "+r"(dh[ah][n][1])
                        : "r"(afr[ah][0]), "r"(afr[ah][1]), "r"(afr[ah][2]), "r"(afr[ah][3]),
                          "r"(bfr[n * 2]), "r"(bfr[n * 2 + 1]));
                }
        }

        // ---- flush fp16 accumulators to fp32 every 4 tiles (<=128 bounded terms) ----
        if ((jt & 3) == 3) {
            #pragma unroll
            for (int ah = 0; ah < 2; ah++)
                #pragma unroll
                for (int n = 0; n < 4; n++) {
                    float2 lo = __half22float2(*(__half2*)&dh[ah][n][0]);
                    float2 hi = __half22float2(*(__half2*)&dh[ah][n][1]);
                    d[ah][n][0] += lo.x; d[ah][n][1] += lo.y;
                    d[ah][n][2] += hi.x; d[ah][n][3] += hi.y;
                    dh[ah][n][0] = 0u;   dh[ah][n][1] = 0u;
                }
        }
    }

    // ---- S: reduce over 16 lanes (col pairs) sharing each row ----
    #pragma unroll
    for (int r = 0; r < 4; r++) {
        float v = sacc[r];
        v += __shfl_xor_sync(0xffffffffu, v, 8);
        v += __shfl_xor_sync(0xffffffffu, v, 4);
        v += __shfl_xor_sync(0xffffffffu, v, 2);
        v += __shfl_xor_sync(0xffffffffu, v, 1);
        if (q == 0) g_Sp[jh][i0 + warp * 8 + rh * 4 + r] = v;
    }

    // ---- store partial D (unnormalized) ----
    float* dp = g_Dp[jh];
    #pragma unroll
    for (int ah = 0; ah < 2; ah++) {
        const int r1 = wi * 32 + ah * 16 + (lane >> 2);
        #pragma unroll
        for (int n = 0; n < 4; n++) {
            const int c = wc * 32 + n * 8 + (lane & 3) * 2;
            *(float2*)&dp[(size_t)(i0 + r1) * OUT_DIM + c]     = make_float2(d[ah][n][0], d[ah][n][1]);
            *(float2*)&dp[(size_t)(i0 + r1 + 8) * OUT_DIM + c] = make_float2(d[ah][n][2], d[ah][n][3]);
        }
    }
}

// ---------------- K5: combine j-halves, normalize, ELU ----------------
__global__ void k_combine(float* __restrict__ out) {
    const int i = blockIdx.x, c = threadIdx.x;
    const float s = g_Sp[0][i] + g_Sp[1][i];
    const size_t idx = (size_t)i * OUT_DIM + c;
    float v = (g_Dp[0][idx] + g_Dp[1][idx]) / s;
    out[idx] = v > 0.f ? v : expm1f(v);
}

// ---------------- launch ----------------
extern "C" void kernel_launch(void* const* d_in, const int* in_sizes, int n_in,
                              void* d_out, int out_size) {
    const float* inp = (const float*)d_in[0];   // [16384, 256]
    const float* adj = (const float*)d_in[1];   // [8192, 16384]
    const float* W   = (const float*)d_in[2];   // [256, 128]
    const float* a   = (const float*)d_in[3];   // [256, 1]
    float* out = (float*)d_out;                 // [8192, 128]

    cudaFuncSetAttribute(k_attn, cudaFuncAttributeMaxDynamicSharedMemorySize, SMEM_BYTES);

    k_gemm1  <<<N_GENES / 8, 128>>>(inp, W);                      // launch 1
    k_wh12   <<<N_GENES / 8, 256>>>(a);                           // launch 2
    k_factors<<<N_GENES / 256, 256>>>();                          // launch 3
    k_attn   <<<(N_REG / TI) * JSPLIT, 256, SMEM_BYTES>>>(adj);   // launch 4 (ncu target)
    k_combine<<<N_REG, OUT_DIM>>>(out);                           // launch 5
}

// round 9
// speedup vs baseline: 1.7814x; 1.7814x over previous
#include <cuda_runtime.h>
#include <cuda_fp16.h>
#include <cstdint>

#define N_GENES 16384
#define N_REG   8192
#define D_MODEL 256
#define OUT_DIM 128
#define ALPHA   0.2f

#define TI 64                    // regulon rows per i-tile
#define TJ 64                    // j per tile (MMA K)
#define NTJ 256                  // j-tiles per i-tile
#define N_ITILES (N_REG / TI)    // 128
#define NJOBS (N_ITILES * NTJ)   // 32768
#define GRID_ATTN 304            // 152 SMs x 2 CTAs

// smem layout (per CTA 80 KB -> 2 CTAs/SM)
#define SM_P    0                      // 2 x 8 KB P double buffer
#define SM_V    16384                  // 4 x 16 KB V stages (fp16, 2 swizzled 64-col atoms)
#define SMEM_BYTES 81920

// ---------------- device scratch ----------------
__device__ float  g_wh [N_GENES * OUT_DIM];
__device__ __align__(16) __half g_whh[N_GENES * OUT_DIM];   // w_h fp16, row-major
__device__ float  g_wh1[N_REG];
__device__ float  g_wh2[N_GENES];
__device__ float  g_F1 [N_GENES];
__device__ float  g_F2 [N_GENES];
__device__ float  g_G1 [N_REG];
__device__ float  g_G2 [N_REG];
__device__ unsigned g_w2max_bits;
__device__ float  g_D  [(size_t)N_REG * OUT_DIM];           // accumulated D (atomics)
__device__ float  g_S  [N_REG];                             // accumulated S (atomics)

// ---------------- helpers ----------------
static __device__ __forceinline__ uint32_t swz(uint32_t x) { return x ^ ((x >> 3) & 0x70); }
static __device__ __forceinline__ uint32_t smem_u32(const void* p) {
    return (uint32_t)__cvta_generic_to_shared(p);
}
static __device__ __forceinline__ uint64_t pk2(float x, float y) {
    uint64_t r; asm("mov.b64 %0, {%1, %2};" : "=l"(r) : "f"(x), "f"(y)); return r;
}
static __device__ __forceinline__ void fma2(uint64_t& acc, uint64_t a, uint64_t b) {
    asm volatile("fma.rn.f32x2 %0, %1, %2, %0;" : "+l"(acc) : "l"(a), "l"(b));
}
static __device__ __forceinline__ unsigned fenc(float f) {
    unsigned u = __float_as_uint(f);
    return (u & 0x80000000u) ? ~u : (u | 0x80000000u);
}
static __device__ __forceinline__ float fdec(unsigned k) {
    unsigned u = (k & 0x80000000u) ? (k ^ 0x80000000u) : ~k;
    return __uint_as_float(u);
}

// ---------------- K1: w_h = input @ weights ----------------
__global__ void k_gemm1(const float* __restrict__ inp, const float* __restrict__ W) {
    __shared__ __align__(16) float s_t[D_MODEL][8];   // [k][r]
    const int c  = threadIdx.x;
    const int r0 = blockIdx.x * 8;
    if (blockIdx.x == 0 && c == 0) g_w2max_bits = 0u;
    #pragma unroll
    for (int u = 0; u < 16; u++) {
        const int idx = c + u * 128;
        const int r = idx >> 8, k = idx & 255;
        s_t[k][r] = inp[(size_t)(r0 + r) * D_MODEL + k];
    }
    __syncthreads();

    uint64_t a01 = 0, a23 = 0, a45 = 0, a67 = 0;
    #pragma unroll 4
    for (int k = 0; k < D_MODEL; k++) {
        const float w = __ldg(&W[k * OUT_DIM + c]);
        const uint64_t ww = pk2(w, w);
        ulonglong2 lo = *(const ulonglong2*)&s_t[k][0];
        ulonglong2 hi = *(const ulonglong2*)&s_t[k][4];
        fma2(a01, lo.x, ww);
        fma2(a23, lo.y, ww);
        fma2(a45, hi.x, ww);
        fma2(a67, hi.y, ww);
    }
    float v[8];
    v[0] = __uint_as_float((uint32_t)a01); v[1] = __uint_as_float((uint32_t)(a01 >> 32));
    v[2] = __uint_as_float((uint32_t)a23); v[3] = __uint_as_float((uint32_t)(a23 >> 32));
    v[4] = __uint_as_float((uint32_t)a45); v[5] = __uint_as_float((uint32_t)(a45 >> 32));
    v[6] = __uint_as_float((uint32_t)a67); v[7] = __uint_as_float((uint32_t)(a67 >> 32));
    #pragma unroll
    for (int r = 0; r < 8; r++) {
        g_wh [(size_t)(r0 + r) * OUT_DIM + c] = v[r];
        g_whh[(size_t)(r0 + r) * OUT_DIM + c] = __float2half(v[r]);
    }
}

// ---------------- K2: wh1, wh2 + global max(wh2) ----------------
__global__ void k_wh12(const float* __restrict__ a) {
    __shared__ float sred[8];
    const int warp = threadIdx.x >> 5;
    const int row  = blockIdx.x * 8 + warp;
    const int lane = threadIdx.x & 31;
    const float* r = g_wh + (size_t)row * OUT_DIM;
    float s1 = 0.f, s2 = 0.f;
    #pragma unroll
    for (int c = lane; c < OUT_DIM; c += 32) {
        float v = r[c];
        s1 = fmaf(v, a[c], s1);
        s2 = fmaf(v, a[OUT_DIM + c], s2);
    }
    #pragma unroll
    for (int o = 16; o; o >>= 1) {
        s1 += __shfl_xor_sync(0xffffffffu, s1, o);
        s2 += __shfl_xor_sync(0xffffffffu, s2, o);
    }
    if (lane == 0) {
        if (row < N_REG) g_wh1[row] = s1;
        g_wh2[row] = s2;
        sred[warp] = s2;
    }
    __syncthreads();
    if (threadIdx.x == 0) {
        float m = sred[0];
        #pragma unroll
        for (int w = 1; w < 8; w++) m = fmaxf(m, sred[w]);
        atomicMax(&g_w2max_bits, fenc(m));
    }
}

// ---------------- K3: exp factor tables + zero D/S accumulators ----------------
__global__ void k_factors() {
    const int j = blockIdx.x * 256 + threadIdx.x;     // 0..16383
    const float w2m = fdec(g_w2max_bits);
    if (j < N_GENES) {
        float w2 = g_wh2[j];
        g_F1[j] = expf(w2);
        g_F2[j] = expf(ALPHA * w2);
    }
    if (j < N_REG) {
        float w1 = g_wh1[j];
        float x  = w1 + w2m;
        float B  = x > 0.f ? x : ALPHA * x;
        g_G1[j] = expf(w1 - B);
        g_G2[j] = expf(ALPHA * w1 - B);
        g_S[j]  = 0.f;
    }
    // zero g_D: 262144 float4, 16 per thread, coalesced
    float4* D4 = (float4*)g_D;
    const float4 z = make_float4(0.f, 0.f, 0.f, 0.f);
    #pragma unroll
    for (int u = 0; u < 16; u++) D4[u * 16384 + j] = z;
}

// ---------------- K4: persistent fused masked-softmax attention ----------------
__global__ void __launch_bounds__(256, 2)
k_attn(const float* __restrict__ adj) {
    extern __shared__ char smem[];
    const uint32_t sb = smem_u32(smem);

    const int t    = threadIdx.x;
    const int lane = t & 31, warp = t >> 5;   // 8 warps
    const int rh   = lane >> 4;               // row half within warp's 8 rows
    const int q    = lane & 15;               // col quad (4 cols)
    const int wi   = warp >> 2, wc = warp & 3;

    // even static partition of the job space
    const int s = (int)(((long long)blockIdx.x * NJOBS) / GRID_ATTN);
    const int e = (int)(((long long)(blockIdx.x + 1) * NJOBS) / GRID_ATTN);

    // V stage loader; ALWAYS commits a group
    auto load_stage = [&](int m) {
        if (m < e) {
            const uint32_t VB = sb + SM_V + (m & 3) * 16384;
            const int jo = (m & (NTJ - 1)) * TJ;
            #pragma unroll
            for (int u = 0; u < 4; u++) {
                const int idx = t + u * 256;
                const int row = idx >> 4, seg = idx & 15;
                const __half* src = &g_whh[(size_t)(jo + row) * OUT_DIM + seg * 8];
                const uint32_t dst = VB + (seg >> 3) * 8192 + swz(row * 128 + (seg & 7) * 16);
                asm volatile("cp.async.cg.shared.global [%0], [%1], 16;" :: "r"(dst), "l"(src));
            }
        }
        asm volatile("cp.async.commit_group;" ::: "memory");
    };

    // adj + factor register prefetch for job m
    float4 av[4], w2q, f1q, f2q;
    auto prefetch = [&](int m) {
        if (m < e) {
            const int jo = (m & (NTJ - 1)) * TJ;
            const float* base = adj + ((size_t)(m >> 8) * TI + warp * 8 + rh * 4) * N_GENES
                              + jo + q * 4;
            #pragma unroll
            for (int r = 0; r < 4; r++)
                av[r] = __ldg((const float4*)(base + (size_t)r * N_GENES));
            w2q = *(const float4*)&g_wh2[jo + q * 4];
            f1q = *(const float4*)&g_F1 [jo + q * 4];
            f2q = *(const float4*)&g_F2 [jo + q * 4];
        }
    };

    float Tr[4], G1r[4], G2r[4], sacc[4];
    float d[2][4][4];
    uint32_t dh[2][4][2];
    int cur_it = -1;

    auto fold = [&]() {   // dh (fp16 pairs) -> d (fp32), reset dh
        #pragma unroll
        for (int ah = 0; ah < 2; ah++)
            #pragma unroll
            for (int n = 0; n < 4; n++) {
                float2 lo = __half22float2(*(__half2*)&dh[ah][n][0]);
                float2 hi = __half22float2(*(__half2*)&dh[ah][n][1]);
                d[ah][n][0] += lo.x; d[ah][n][1] += lo.y;
                d[ah][n][2] += hi.x; d[ah][n][3] += hi.y;
                dh[ah][n][0] = 0u;   dh[ah][n][1] = 0u;
            }
    };

    auto flush = [&](int it) {   // publish partial S and D for i-tile it
        fold();
        #pragma unroll
        for (int r = 0; r < 4; r++) {
            float v = sacc[r];
            v += __shfl_xor_sync(0xffffffffu, v, 8);
            v += __shfl_xor_sync(0xffffffffu, v, 4);
            v += __shfl_xor_sync(0xffffffffu, v, 2);
            v += __shfl_xor_sync(0xffffffffu, v, 1);
            if (q == 0) atomicAdd(&g_S[it * TI + warp * 8 + rh * 4 + r], v);
        }
        #pragma unroll
        for (int ah = 0; ah < 2; ah++) {
            const int r1 = wi * 32 + ah * 16 + (lane >> 2);
            #pragma unroll
            for (int n = 0; n < 4; n++) {
                const int c = wc * 32 + n * 8 + (lane & 3) * 2;
                float* p0 = &g_D[(size_t)(it * TI + r1) * OUT_DIM + c];
                float* p1 = &g_D[(size_t)(it * TI + r1 + 8) * OUT_DIM + c];
                atomicAdd(p0,     d[ah][n][0]);
                atomicAdd(p0 + 1, d[ah][n][1]);
                atomicAdd(p1,     d[ah][n][2]);
                atomicAdd(p1 + 1, d[ah][n][3]);
            }
        }
    };

    auto reset_acc = [&]() {
        #pragma unroll
        for (int ah = 0; ah < 2; ah++)
            #pragma unroll
            for (int n = 0; n < 4; n++) {
                d[ah][n][0] = d[ah][n][1] = d[ah][n][2] = d[ah][n][3] = 0.f;
                dh[ah][n][0] = dh[ah][n][1] = 0u;
            }
        #pragma unroll
        for (int r = 0; r < 4; r++) sacc[r] = 0.f;
    };

    prefetch(s);
    load_stage(s);
    load_stage(s + 1);
    load_stage(s + 2);

    for (int m = s; m < e; m++) {
        const uint32_t PB = sb + SM_P + (m & 1) * 8192;
        const uint32_t VB = sb + SM_V + (m & 3) * 16384;

        asm volatile("cp.async.wait_group 2;" ::: "memory");
        __syncthreads();

        load_stage(m + 3);

        const int it = m >> 8;
        if (it != cur_it) {           // i-tile boundary (uniform across CTA)
            if (cur_it >= 0) flush(cur_it);
            cur_it = it;
            #pragma unroll
            for (int r = 0; r < 4; r++) {
                const int i = it * TI + warp * 8 + rh * 4 + r;
                Tr[r]  = g_wh1[i];
                G1r[r] = g_G1[i];
                G2r[r] = g_G2[i];
            }
            reset_acc();
        }

        // ---- build P tile (4 rows x 4 cols per thread) ----
        #pragma unroll
        for (int r = 0; r < 4; r++) {
            const float T = Tr[r], G1 = G1r[r], G2 = G2r[r];
            float x0 = T + w2q.x, x1 = T + w2q.y, x2 = T + w2q.z, x3 = T + w2q.w;
            float e0 = fmaxf(G1 * f1q.x, G2 * f2q.x);   // exp(lrelu(x)-B), monotone split
            float e1 = fmaxf(G1 * f1q.y, G2 * f2q.y);
            float e2 = fmaxf(G1 * f1q.z, G2 * f2q.z);
            float e3 = fmaxf(G1 * f1q.w, G2 * f2q.w);
            float p0 = (av[r].x != 0.f && x0 != 0.f) ? e0 : 0.f;
            float p1 = (av[r].y != 0.f && x1 != 0.f) ? e1 : 0.f;
            float p2 = (av[r].z != 0.f && x2 != 0.f) ? e2 : 0.f;
            float p3 = (av[r].w != 0.f && x3 != 0.f) ? e3 : 0.f;
            sacc[r] += (p0 + p1) + (p2 + p3);
            __half2 h01 = __floats2half2_rn(p0, p1);
            __half2 h23 = __floats2half2_rn(p2, p3);
            asm volatile("st.shared.v2.b32 [%0], {%1, %2};"
                         :: "r"(PB + swz((warp * 8 + rh * 4 + r) * 128 + q * 8)),
                            "r"(*(uint32_t*)&h01), "r"(*(uint32_t*)&h23));
        }

        prefetch(m + 1);   // hidden under MMA + next wait
        __syncthreads();   // P complete

        // ---- MMA: D(32x32 per warp) += P(32x64) @ V(64x32), fp16 accumulate ----
        #pragma unroll
        for (int ks = 0; ks < 4; ks++) {
            uint32_t afr[2][4];
            #pragma unroll
            for (int ah = 0; ah < 2; ah++) {
                const uint32_t aaddr = PB + swz((wi * 32 + ah * 16 + (lane & 15)) * 128
                                                + ks * 32 + (lane >> 4) * 16);
                asm volatile("ldmatrix.sync.aligned.m8n8.x4.shared.b16 {%0,%1,%2,%3},[%4];\n"
                             : "=r"(afr[ah][0]), "=r"(afr[ah][1]),
                               "=r"(afr[ah][2]), "=r"(afr[ah][3]) : "r"(aaddr));
            }
            uint32_t bfr[8];
            const int atom = wc >> 1;
            const int cin0 = (wc & 1) * 32 + (lane >> 4) * 8;
            const uint32_t brow = (ks * 16 + (lane & 15)) * 128;
            const uint32_t baddr0 = VB + atom * 8192 + swz(brow + cin0 * 2);
            asm volatile("ldmatrix.sync.aligned.m8n8.x4.trans.shared.b16 {%0,%1,%2,%3},[%4];\n"
                         : "=r"(bfr[0]), "=r"(bfr[1]), "=r"(bfr[2]), "=r"(bfr[3]) : "r"(baddr0));
            const uint32_t baddr1 = VB + atom * 8192 + swz(brow + (cin0 + 16) * 2);
            asm volatile("ldmatrix.sync.aligned.m8n8.x4.trans.shared.b16 {%0,%1,%2,%3},[%4];\n"
                         : "=r"(bfr[4]), "=r"(bfr[5]), "=r"(bfr[6]), "=r"(bfr[7]) : "r"(baddr1));
            #pragma unroll
            for (int ah = 0; ah < 2; ah++)
                #pragma unroll
                for (int n = 0; n < 4; n++) {
                    asm volatile(
                        "mma.sync.aligned.m16n8k16.row.col.f16.f16.f16.f16 "
                        "{%0,%1},{%2,%3,%4,%5},{%6,%7},{%0,%1};\n"
                        : "+r"(dh[ah][n][0]), "+r"(dh[ah][n][1])
                        : "r"(afr[ah][0]), "r"(afr[ah][1]), "r"(afr[ah][2]), "r"(afr[ah][3]),
                          "r"(bfr[n * 2]), "r"(bfr[n * 2 + 1]));
                }
        }

        // fold fp16 accumulators to fp32 every 2 tiles (<=128 bounded terms);
        // i-tile boundaries are at m % 256 == 0, so dh is always folded there
        if (m & 1) fold();
    }

    flush(cur_it);   // final partial (fold() inside handles pending dh)
}

// ---------------- K5: normalize + ELU ----------------
__global__ void k_combine(float* __restrict__ out) {
    const int i = blockIdx.x, c = threadIdx.x;
    const float s = g_S[i];
    const size_t idx = (size_t)i * OUT_DIM + c;
    float v = g_D[idx] / s;
    out[idx] = v > 0.f ? v : expm1f(v);
}

// ---------------- launch ----------------
extern "C" void kernel_launch(void* const* d_in, const int* in_sizes, int n_in,
                              void* d_out, int out_size) {
    const float* inp = (const float*)d_in[0];   // [16384, 256]
    const float* adj = (const float*)d_in[1];   // [8192, 16384]
    const float* W   = (const float*)d_in[2];   // [256, 128]
    const float* a   = (const float*)d_in[3];   // [256, 1]
    float* out = (float*)d_out;                 // [8192, 128]

    cudaFuncSetAttribute(k_attn, cudaFuncAttributeMaxDynamicSharedMemorySize, SMEM_BYTES);

    k_gemm1  <<<N_GENES / 8, 128>>>(inp, W);          // launch 1
    k_wh12   <<<N_GENES / 8, 256>>>(a);               // launch 2
    k_factors<<<N_GENES / 256, 256>>>();              // launch 3 (also zeroes D/S)
    k_attn   <<<GRID_ATTN, 256, SMEM_BYTES>>>(adj);   // launch 4 (ncu target)
    k_combine<<<N_REG, OUT_DIM>>>(out);               // launch 5
}

// round 10
// speedup vs baseline: 1.9066x; 1.0703x over previous
#include <cuda_runtime.h>
#include <cuda_fp16.h>
#include <cstdint>

#define N_GENES 16384
#define N_REG   8192
#define D_MODEL 256
#define OUT_DIM 128
#define ALPHA   0.2f

#define TI 64                    // regulon rows per i-tile
#define TJ 64                    // j per tile (MMA K)
#define NTJ 256                  // j-tiles per i-tile
#define N_ITILES (N_REG / TI)    // 128
#define NJOBS (N_ITILES * NTJ)   // 32768
#define GRID_ATTN 304            // 152 SMs x 2 CTAs

// smem layout (per CTA 80 KB -> 2 CTAs/SM)
#define SM_P    0                      // 2 x 8 KB P double buffer
#define SM_V    16384                  // 4 x 16 KB V stages (fp16, 2 swizzled 64-col atoms)
#define SMEM_BYTES 81920

// ---------------- device scratch ----------------
__device__ __align__(16) __half g_whh[N_GENES * OUT_DIM];   // w_h fp16, row-major
__device__ float  g_wh1[N_REG];
__device__ float  g_wh2[N_GENES];
__device__ float  g_F1 [N_GENES];
__device__ float  g_F2 [N_GENES];
__device__ float  g_G1 [N_REG];
__device__ float  g_G2 [N_REG];
__device__ unsigned g_w2max_bits;
__device__ float  g_D  [(size_t)N_REG * OUT_DIM];           // accumulated D (atomics)
__device__ float  g_S  [N_REG];                             // accumulated S (atomics)

// ---------------- helpers ----------------
static __device__ __forceinline__ uint32_t swz(uint32_t x) { return x ^ ((x >> 3) & 0x70); }
static __device__ __forceinline__ uint32_t smem_u32(const void* p) {
    return (uint32_t)__cvta_generic_to_shared(p);
}
static __device__ __forceinline__ uint64_t pk2(float x, float y) {
    uint64_t r; asm("mov.b64 %0, {%1, %2};" : "=l"(r) : "f"(x), "f"(y)); return r;
}
static __device__ __forceinline__ void fma2(uint64_t& acc, uint64_t a, uint64_t b) {
    asm volatile("fma.rn.f32x2 %0, %1, %2, %0;" : "+l"(acc) : "l"(a), "l"(b));
}
static __device__ __forceinline__ unsigned fenc(float f) {
    unsigned u = __float_as_uint(f);
    return (u & 0x80000000u) ? ~u : (u | 0x80000000u);
}
static __device__ __forceinline__ float fdec(unsigned k) {
    unsigned u = (k & 0x80000000u) ? (k ^ 0x80000000u) : ~k;
    return __uint_as_float(u);
}

// ---------------- K1: w_h = input @ W  (+fused wh1/wh2/max) ----------------
__global__ void k_gemm1(const float* __restrict__ inp, const float* __restrict__ W,
                        const float* __restrict__ a) {
    __shared__ __align__(16) float s_t[D_MODEL][8];   // [k][r]
    __shared__ float sred[4][16];
    const int c  = threadIdx.x;          // 0..127
    const int r0 = blockIdx.x * 8;
    if (blockIdx.x == 0 && c == 0) g_w2max_bits = 0u;   // long gap before any atomicMax
    #pragma unroll
    for (int u = 0; u < 16; u++) {
        const int idx = c + u * 128;
        const int r = idx >> 8, k = idx & 255;
        s_t[k][r] = inp[(size_t)(r0 + r) * D_MODEL + k];
    }
    __syncthreads();

    uint64_t a01 = 0, a23 = 0, a45 = 0, a67 = 0;
    #pragma unroll 4
    for (int k = 0; k < D_MODEL; k++) {
        const float w = __ldg(&W[k * OUT_DIM + c]);
        const uint64_t ww = pk2(w, w);
        ulonglong2 lo = *(const ulonglong2*)&s_t[k][0];
        ulonglong2 hi = *(const ulonglong2*)&s_t[k][4];
        fma2(a01, lo.x, ww);
        fma2(a23, lo.y, ww);
        fma2(a45, hi.x, ww);
        fma2(a67, hi.y, ww);
    }
    float v[8];
    v[0] = __uint_as_float((uint32_t)a01); v[1] = __uint_as_float((uint32_t)(a01 >> 32));
    v[2] = __uint_as_float((uint32_t)a23); v[3] = __uint_as_float((uint32_t)(a23 >> 32));
    v[4] = __uint_as_float((uint32_t)a45); v[5] = __uint_as_float((uint32_t)(a45 >> 32));
    v[6] = __uint_as_float((uint32_t)a67); v[7] = __uint_as_float((uint32_t)(a67 >> 32));
    #pragma unroll
    for (int r = 0; r < 8; r++)
        g_whh[(size_t)(r0 + r) * OUT_DIM + c] = __float2half(v[r]);

    // fused wh1/wh2: s1[r] = <wh_r, a[:128]>, s2[r] = <wh_r, a[128:]>
    const float a1 = a[c], a2 = a[OUT_DIM + c];
    const int warp = c >> 5, lane = c & 31;
    #pragma unroll
    for (int r = 0; r < 8; r++) {
        float u1 = v[r] * a1, u2 = v[r] * a2;
        #pragma unroll
        for (int o = 16; o; o >>= 1) {
            u1 += __shfl_xor_sync(0xffffffffu, u1, o);
            u2 += __shfl_xor_sync(0xffffffffu, u2, o);
        }
        if (lane == 0) { sred[warp][r] = u1; sred[warp][8 + r] = u2; }
    }
    __syncthreads();
    if (c < 32) {
        float val = (c < 16) ? (sred[0][c] + sred[1][c] + sred[2][c] + sred[3][c]) : -1e30f;
        if (c < 8) { if (r0 + c < N_REG) g_wh1[r0 + c] = val; }
        else if (c < 16) g_wh2[r0 + c - 8] = val;
        float m = (c >= 8 && c < 16) ? val : -1e30f;
        #pragma unroll
        for (int o = 16; o; o >>= 1) m = fmaxf(m, __shfl_xor_sync(0xffffffffu, m, o));
        if (c == 0) atomicMax(&g_w2max_bits, fenc(m));
    }
}

// ---------------- K2: F1/F2 tables + zero D ----------------
__global__ void k_factorsA() {
    const int j = blockIdx.x * 256 + threadIdx.x;     // 0..16383
    float w2 = g_wh2[j];
    g_F1[j] = expf(w2);
    g_F2[j] = expf(ALPHA * w2);
    float4* D4 = (float4*)g_D;
    const float4 z = make_float4(0.f, 0.f, 0.f, 0.f);
    #pragma unroll
    for (int u = 0; u < 16; u++) D4[u * 16384 + j] = z;
}

// ---------------- K3: G1/G2 tables + zero S ----------------
__global__ void k_factorsB() {
    const int j = blockIdx.x * 256 + threadIdx.x;     // 0..8191
    const float w2m = fdec(g_w2max_bits);
    float w1 = g_wh1[j];
    float x  = w1 + w2m;
    float B  = x > 0.f ? x : ALPHA * x;
    g_G1[j] = expf(w1 - B);
    g_G2[j] = expf(ALPHA * w1 - B);
    g_S[j]  = 0.f;
}

// ---------------- K4: persistent fused masked-softmax attention (skewed pipeline) --------
__global__ void __launch_bounds__(256, 2)
k_attn(const float* __restrict__ adj) {
    extern __shared__ char smem[];
    const uint32_t sb = smem_u32(smem);

    const int t    = threadIdx.x;
    const int lane = t & 31, warp = t >> 5;   // 8 warps
    const int rh   = lane >> 4;               // row half within warp's 8 rows
    const int q    = lane & 15;               // col quad (4 cols)
    const int wi   = warp >> 2, wc = warp & 3;

    // even static partition of the job space
    const int s = (int)(((long long)blockIdx.x * NJOBS) / GRID_ATTN);
    const int e = (int)(((long long)(blockIdx.x + 1) * NJOBS) / GRID_ATTN);

    // V stage loader; ALWAYS commits a group
    auto load_stage = [&](int m) {
        if (m < e) {
            const uint32_t VB = sb + SM_V + (m & 3) * 16384;
            const int jo = (m & (NTJ - 1)) * TJ;
            #pragma unroll
            for (int u = 0; u < 4; u++) {
                const int idx = t + u * 256;
                const int row = idx >> 4, seg = idx & 15;
                const __half* src = &g_whh[(size_t)(jo + row) * OUT_DIM + seg * 8];
                const uint32_t dst = VB + (seg >> 3) * 8192 + swz(row * 128 + (seg & 7) * 16);
                asm volatile("cp.async.cg.shared.global [%0], [%1], 16;" :: "r"(dst), "l"(src));
            }
        }
        asm volatile("cp.async.commit_group;" ::: "memory");
    };

    // adj + factor register prefetch for job m
    float4 av[4], w2q, f1q, f2q;
    auto prefetch = [&](int m) {
        if (m < e) {
            const int jo = (m & (NTJ - 1)) * TJ;
            const float* base = adj + ((size_t)(m >> 8) * TI + warp * 8 + rh * 4) * N_GENES
                              + jo + q * 4;
            #pragma unroll
            for (int r = 0; r < 4; r++)
                av[r] = __ldg((const float4*)(base + (size_t)r * N_GENES));
            w2q = *(const float4*)&g_wh2[jo + q * 4];
            f1q = *(const float4*)&g_F1 [jo + q * 4];
            f2q = *(const float4*)&g_F2 [jo + q * 4];
        }
    };

    float Tr[4], G1r[4], G2r[4], sacc[4];
    float d[2][4][4];
    uint32_t dh[2][4][2];

    auto load_row_consts = [&](int it) {
        #pragma unroll
        for (int r = 0; r < 4; r++) {
            const int i = it * TI + warp * 8 + rh * 4 + r;
            Tr[r]  = g_wh1[i];
            G1r[r] = g_G1[i];
            G2r[r] = g_G2[i];
            sacc[r] = 0.f;
        }
    };
    auto reset_D = [&]() {
        #pragma unroll
        for (int ah = 0; ah < 2; ah++)
            #pragma unroll
            for (int n = 0; n < 4; n++) {
                d[ah][n][0] = d[ah][n][1] = d[ah][n][2] = d[ah][n][3] = 0.f;
                dh[ah][n][0] = dh[ah][n][1] = 0u;
            }
    };
    auto fold = [&]() {
        #pragma unroll
        for (int ah = 0; ah < 2; ah++)
            #pragma unroll
            for (int n = 0; n < 4; n++) {
                float2 lo = __half22float2(*(__half2*)&dh[ah][n][0]);
                float2 hi = __half22float2(*(__half2*)&dh[ah][n][1]);
                d[ah][n][0] += lo.x; d[ah][n][1] += lo.y;
                d[ah][n][2] += hi.x; d[ah][n][3] += hi.y;
                dh[ah][n][0] = 0u;   dh[ah][n][1] = 0u;
            }
    };
    auto flush_S = [&](int it) {
        #pragma unroll
        for (int r = 0; r < 4; r++) {
            float v = sacc[r];
            v += __shfl_xor_sync(0xffffffffu, v, 8);
            v += __shfl_xor_sync(0xffffffffu, v, 4);
            v += __shfl_xor_sync(0xffffffffu, v, 2);
            v += __shfl_xor_sync(0xffffffffu, v, 1);
            if (q == 0) atomicAdd(&g_S[it * TI + warp * 8 + rh * 4 + r], v);
        }
    };
    auto flush_D = [&](int it) {
        fold();
        #pragma unroll
        for (int ah = 0; ah < 2; ah++) {
            const int r1 = wi * 32 + ah * 16 + (lane >> 2);
            #pragma unroll
            for (int n = 0; n < 4; n++) {
                const int c = wc * 32 + n * 8 + (lane & 3) * 2;
                float* p0 = &g_D[(size_t)(it * TI + r1) * OUT_DIM + c];
                float* p1 = &g_D[(size_t)(it * TI + r1 + 8) * OUT_DIM + c];
                atomicAdd(p0,     d[ah][n][0]);
                atomicAdd(p0 + 1, d[ah][n][1]);
                atomicAdd(p1,     d[ah][n][2]);
                atomicAdd(p1 + 1, d[ah][n][3]);
                d[ah][n][0] = d[ah][n][1] = d[ah][n][2] = d[ah][n][3] = 0.f;
            }
        }
    };
    // build P tile for job m into PB[m&1] from av/w2q/f1q/f2q regs; accumulates sacc
    auto build_P = [&](int m) {
        const uint32_t PB = sb + SM_P + (m & 1) * 8192;
        #pragma unroll
        for (int r = 0; r < 4; r++) {
            const float T = Tr[r], G1 = G1r[r], G2 = G2r[r];
            float x0 = T + w2q.x, x1 = T + w2q.y, x2 = T + w2q.z, x3 = T + w2q.w;
            float e0 = fmaxf(G1 * f1q.x, G2 * f2q.x);   // exp(lrelu(x)-B), monotone split
            float e1 = fmaxf(G1 * f1q.y, G2 * f2q.y);
            float e2 = fmaxf(G1 * f1q.z, G2 * f2q.z);
            float e3 = fmaxf(G1 * f1q.w, G2 * f2q.w);
            float p0 = (av[r].x != 0.f && x0 != 0.f) ? e0 : 0.f;
            float p1 = (av[r].y != 0.f && x1 != 0.f) ? e1 : 0.f;
            float p2 = (av[r].z != 0.f && x2 != 0.f) ? e2 : 0.f;
            float p3 = (av[r].w != 0.f && x3 != 0.f) ? e3 : 0.f;
            sacc[r] += (p0 + p1) + (p2 + p3);
            __half2 h01 = __floats2half2_rn(p0, p1);
            __half2 h23 = __floats2half2_rn(p2, p3);
            asm volatile("st.shared.v2.b32 [%0], {%1, %2};"
                         :: "r"(PB + swz((warp * 8 + rh * 4 + r) * 128 + q * 8)),
                            "r"(*(uint32_t*)&h01), "r"(*(uint32_t*)&h23));
        }
    };

    // ---- prologue ----
    prefetch(s);
    load_stage(s);
    load_stage(s + 1);
    load_stage(s + 2);
    int it_b = s >> 8;           // build-side i-tile
    load_row_consts(it_b);
    reset_D();
    build_P(s);
    prefetch(s + 1);

    // ---- main loop: one barrier per tile; build P[m+1] overlaps MMA[m] ----
    for (int m = s; m < e; m++) {
        const uint32_t PB = sb + SM_P + (m & 1) * 8192;
        const uint32_t VB = sb + SM_V + (m & 3) * 16384;

        asm volatile("cp.async.wait_group 2;" ::: "memory");   // V[m] resident
        __syncthreads();   // P[m] visible; MMA m-1 done -> PB[(m+1)&1] + V slot free

        load_stage(m + 3);

        if (m + 1 < e) {
            const int it_n = (m + 1) >> 8;
            if (it_n != it_b) {          // build crosses i-tile boundary
                flush_S(it_b);
                it_b = it_n;
                load_row_consts(it_b);   // also resets sacc
            }
            build_P(m + 1);
            prefetch(m + 2);
        }

        // ---- MMA: D(32x32 per warp) += P(32x64) @ V(64x32), fp16 accumulate ----
        #pragma unroll
        for (int ks = 0; ks < 4; ks++) {
            uint32_t afr[2][4];
            #pragma unroll
            for (int ah = 0; ah < 2; ah++) {
                const uint32_t aaddr = PB + swz((wi * 32 + ah * 16 + (lane & 15)) * 128
                                                + ks * 32 + (lane >> 4) * 16);
                asm volatile("ldmatrix.sync.aligned.m8n8.x4.shared.b16 {%0,%1,%2,%3},[%4];\n"
                             : "=r"(afr[ah][0]), "=r"(afr[ah][1]),
                               "=r"(afr[ah][2]), "=r"(afr[ah][3]) : "r"(aaddr));
            }
            uint32_t bfr[8];
            const int atom = wc >> 1;
            const int cin0 = (wc & 1) * 32 + (lane >> 4) * 8;
            const uint32_t brow = (ks * 16 + (lane & 15)) * 128;
            const uint32_t baddr0 = VB + atom * 8192 + swz(brow + cin0 * 2);
            asm volatile("ldmatrix.sync.aligned.m8n8.x4.trans.shared.b16 {%0,%1,%2,%3},[%4];\n"
                         : "=r"(bfr[0]), "=r"(bfr[1]), "=r"(bfr[2]), "=r"(bfr[3]) : "r"(baddr0));
            const uint32_t baddr1 = VB + atom * 8192 + swz(brow + (cin0 + 16) * 2);
            asm volatile("ldmatrix.sync.aligned.m8n8.x4.trans.shared.b16 {%0,%1,%2,%3},[%4];\n"
                         : "=r"(bfr[4]), "=r"(bfr[5]), "=r"(bfr[6]), "=r"(bfr[7]) : "r"(baddr1));
            #pragma unroll
            for (int ah = 0; ah < 2; ah++)
                #pragma unroll
                for (int n = 0; n < 4; n++) {
                    asm volatile(
                        "mma.sync.aligned.m16n8k16.row.col.f16.f16.f16.f16 "
                        "{%0,%1},{%2,%3,%4,%5},{%6,%7},{%0,%1};\n"
                        : "+r"(dh[ah][n][0]), "+r"(dh[ah][n][1])
                        : "r"(afr[ah][0]), "r"(afr[ah][1]), "r"(afr[ah][2]), "r"(afr[ah][3]),
                          "r"(bfr[n * 2]), "r"(bfr[n * 2 + 1]));
                }
        }

        // D flush at i-tile end (or range end); else fold fp16->fp32 every 2 tiles
        const int it_m = m >> 8;
        if (m + 1 == e || ((m + 1) >> 8) != it_m) {
            flush_D(it_m);                 // fold() inside; resets d/dh
        } else if (m & 1) {
            fold();
        }
    }
    flush_S(it_b);   // last i-tile's S (sacc final)
}

// ---------------- K5: normalize + ELU ----------------
__global__ void k_combine(float* __restrict__ out) {
    const int i = blockIdx.x, c = threadIdx.x;
    const float s = g_S[i];
    const size_t idx = (size_t)i * OUT_DIM + c;
    float v = g_D[idx] / s;
    out[idx] = v > 0.f ? v : expm1f(v);
}

// ---------------- launch ----------------
extern "C" void kernel_launch(void* const* d_in, const int* in_sizes, int n_in,
                              void* d_out, int out_size) {
    const float* inp = (const float*)d_in[0];   // [16384, 256]
    const float* adj = (const float*)d_in[1];   // [8192, 16384]
    const float* W   = (const float*)d_in[2];   // [256, 128]
    const float* a   = (const float*)d_in[3];   // [256, 1]
    float* out = (float*)d_out;                 // [8192, 128]

    cudaFuncSetAttribute(k_attn, cudaFuncAttributeMaxDynamicSharedMemorySize, SMEM_BYTES);

    k_gemm1   <<<N_GENES / 8, 128>>>(inp, W, a);       // launch 1 (fused wh1/wh2/max)
    k_factorsA<<<N_GENES / 256, 256>>>();              // launch 2 (F tables + zero D)
    k_factorsB<<<N_REG / 256, 256>>>();                // launch 3 (G tables + zero S)
    k_attn    <<<GRID_ATTN, 256, SMEM_BYTES>>>(adj);   // launch 4 (ncu target)
    k_combine <<<N_REG, OUT_DIM>>>(out);               // launch 5
}